// round 6
// baseline (speedup 1.0000x reference)
#include <cuda_runtime.h>
#include <cuda_fp16.h>

#define N_NODES 100000
#define E_EDGES 1600000
#define IN_DIM 32
#define HID 64
#define NHEADS 2
#define F1 128   // NHEADS*HID
#define OUTC 64
#define LOG2E 1.4426950408889634f

#define CSR_BLOCKS 512
#define CSR_THREADS 256

// ---------------- scratch (device globals; no allocation allowed) ------------
__device__ __align__(16) __half g_h1h [(size_t)(N_NODES + 1) * F1];
__device__ __align__(16) __half g_hlnh[(size_t)N_NODES * F1];
__device__ __align__(16) __half g_h2h [(size_t)(N_NODES + 1) * OUTC];
__device__ __align__(16) float g_as1[(N_NODES + 1) * NHEADS];
__device__ __align__(16) float g_ad1[(N_NODES + 1) * NHEADS];
__device__ float g_as2[N_NODES + 1];
__device__ float g_ad2[N_NODES + 1];
__device__ int   g_deg[N_NODES];
__device__ int   g_off[N_NODES + 1];
__device__ int   g_cur[N_NODES];
__device__ __align__(16) int g_csr[E_EDGES + 3 * N_NODES + 8];
__device__ int   g_bsum[CSR_BLOCKS];
__device__ int   g_bscan[CSR_BLOCKS];
__device__ __align__(16) float g_was2[F1];
__device__ __align__(16) float g_wad2[F1];
__device__ int   g_bar_count;
__device__ int   g_bar_gen;

__device__ __forceinline__ float lrelu(float v) { return v > 0.f ? v : 0.2f * v; }

// ---- packed fp32x2 helpers ----------------------------------------------------
__device__ __forceinline__ unsigned long long packdup(float a) {
    unsigned long long r;
    asm("mov.b64 %0, {%1, %1};" : "=l"(r) : "f"(a));
    return r;
}
__device__ __forceinline__ void ffma2(unsigned long long& acc,
                                      unsigned long long a, unsigned long long b) {
    asm("fma.rn.f32x2 %0, %1, %2, %0;" : "+l"(acc) : "l"(a), "l"(b));
}
__device__ __forceinline__ float lo32(unsigned long long v) {
    return __uint_as_float((unsigned)(v & 0xffffffffull));
}
__device__ __forceinline__ float hi32(unsigned long long v) {
    return __uint_as_float((unsigned)(v >> 32));
}

// ---- software grid barrier ----------------------------------------------------
__device__ __forceinline__ void gsync() {
    __syncthreads();
    __threadfence();
    if (threadIdx.x == 0) {
        int gen = *(volatile int*)&g_bar_gen;
        if (atomicAdd(&g_bar_count, 1) == CSR_BLOCKS - 1) {
            g_bar_count = 0;
            __threadfence();
            *(volatile int*)&g_bar_gen = gen + 1;
        } else {
            while (*(volatile int*)&g_bar_gen == gen) { }
        }
        __threadfence();
    }
    __syncthreads();
}

// ------- fused CSR build: zero + degree + scan(pad4) + pad-fill + scatter ------
__global__ void __launch_bounds__(CSR_THREADS, 8)
k_csr(const int* __restrict__ src, const int* __restrict__ dst, int E, int n) {
    const int T = CSR_BLOCKS * CSR_THREADS;
    int t = threadIdx.x;
    int gt = blockIdx.x * CSR_THREADS + t;
    int lane = t & 31, w = t >> 5;
    __shared__ int wsum[8];

    for (int i = gt; i < n; i += T) g_deg[i] = 0;
    gsync();
    int E4 = E >> 2;
    for (int i = gt; i < E4; i += T) {
        int4 d4 = ((const int4*)dst)[i];
        atomicAdd(&g_deg[d4.x], 1);
        atomicAdd(&g_deg[d4.y], 1);
        atomicAdd(&g_deg[d4.z], 1);
        atomicAdd(&g_deg[d4.w], 1);
    }
    for (int e = E4 * 4 + gt; e < E; e += T) atomicAdd(&g_deg[dst[e]], 1);
    gsync();
    int C = (n + T - 1) / T;
    int b0 = gt * C;
    int s = 0;
    for (int i = 0; i < C; ++i) {
        int idx = b0 + i;
        if (idx < n) s += (g_deg[idx] + 3) & ~3;
    }
    int incl = s;
    #pragma unroll
    for (int o = 1; o < 32; o <<= 1) {
        int xv = __shfl_up_sync(0xffffffffu, incl, o);
        if (lane >= o) incl += xv;
    }
    if (lane == 31) wsum[w] = incl;
    __syncthreads();
    if (t < 8) {
        int xv = wsum[t];
        #pragma unroll
        for (int o = 1; o < 8; o <<= 1) {
            int y = __shfl_up_sync(0xffu, xv, o);
            if (t >= o) xv += y;
        }
        wsum[t] = xv;
    }
    __syncthreads();
    int excl = incl - s + (w > 0 ? wsum[w - 1] : 0);
    if (t == CSR_THREADS - 1) g_bsum[blockIdx.x] = excl + s;
    gsync();
    if (blockIdx.x == 0) {
        int a0 = g_bsum[2 * t], a1 = g_bsum[2 * t + 1];
        int ss = a0 + a1;
        int in2 = ss;
        #pragma unroll
        for (int o = 1; o < 32; o <<= 1) {
            int xv = __shfl_up_sync(0xffffffffu, in2, o);
            if (lane >= o) in2 += xv;
        }
        if (lane == 31) wsum[w] = in2;
        __syncthreads();
        if (t < 8) {
            int xv = wsum[t];
            #pragma unroll
            for (int o = 1; o < 8; o <<= 1) {
                int y = __shfl_up_sync(0xffu, xv, o);
                if (t >= o) xv += y;
            }
            wsum[t] = xv;
        }
        __syncthreads();
        int ex2 = in2 - ss + (w > 0 ? wsum[w - 1] : 0);
        g_bscan[2 * t]     = ex2;
        g_bscan[2 * t + 1] = ex2 + a0;
    }
    gsync();
    int off = excl + g_bscan[blockIdx.x];
    for (int i = 0; i < C; ++i) {
        int idx = b0 + i;
        if (idx < n) {
            int d = g_deg[idx];
            int p = (d + 3) & ~3;
            g_off[idx] = off;
            g_cur[idx] = off;
            for (int j = d; j < p; ++j) g_csr[off + j] = n;  // dummy
            if (idx == n - 1) g_off[n] = off + p;
            off += p;
        }
    }
    gsync();
    for (int i = gt; i < E4; i += T) {
        int4 s4 = ((const int4*)src)[i];
        int4 d4 = ((const int4*)dst)[i];
        g_csr[atomicAdd(&g_cur[d4.x], 1)] = s4.x;
        g_csr[atomicAdd(&g_cur[d4.y], 1)] = s4.y;
        g_csr[atomicAdd(&g_cur[d4.z], 1)] = s4.z;
        g_csr[atomicAdd(&g_cur[d4.w], 1)] = s4.w;
    }
    for (int e = E4 * 4 + gt; e < E; e += T) {
        g_csr[atomicAdd(&g_cur[dst[e]], 1)] = src[e];
    }
}

// ------- layer-2 attention fold + dummy-node init ------------------------------
__global__ void k_fold2(const float* __restrict__ W2,
                        const float* __restrict__ as2, const float* __restrict__ ad2, int n) {
    int t = threadIdx.x;  // 128
    float s = 0.f, d = 0.f;
    for (int c = 0; c < OUTC; ++c) {
        float w = W2[t * OUTC + c];
        s += w * as2[c];
        d += w * ad2[c];
    }
    g_was2[t] = s;
    g_wad2[t] = d;
    if (t < 2) { g_as1[2 * n + t] = -1e30f; g_ad1[2 * n + t] = 0.f; }
    if (t == 0) { g_as2[n] = -1e30f; g_ad2[n] = 0.f; }
    g_h1h[(size_t)n * F1 + t] = __float2half(0.f);
    if (t < OUTC) g_h2h[(size_t)n * OUTC + t] = __float2half(0.f);
}

// ---------------- layer-1 projection + logits (prescaled by log2e) -------------
__global__ void k1_proj(const float* __restrict__ x, const float* __restrict__ W1,
                        const float* __restrict__ attS, const float* __restrict__ attD, int n) {
    __shared__ __align__(16) float Ws[IN_DIM * F1];
    __shared__ __align__(16) float xsT[IN_DIM][36];
    int t = threadIdx.x;                                // 256
    for (int i = t; i < IN_DIM * F1; i += 256) Ws[i] = W1[i];
    int base = blockIdx.x * 32;
    #pragma unroll
    for (int i = 0; i < 4; ++i) {
        int idx = t + i * 256;
        int node = idx >> 5, k = idx & 31;
        int nn = base + node;
        xsT[k][node] = (nn < n) ? x[(size_t)nn * IN_DIM + k] : 0.f;
    }
    __syncthreads();
    int tx = t & 31;
    int ty = t >> 5;
    unsigned long long acc[4][2] = {};
    #pragma unroll
    for (int k = 0; k < IN_DIM; ++k) {
        ulonglong2 w = *(const ulonglong2*)&Ws[k * F1 + tx * 4];
        float4 xv = *(const float4*)&xsT[k][ty * 4];
        unsigned long long xp0 = packdup(xv.x), xp1 = packdup(xv.y);
        unsigned long long xp2 = packdup(xv.z), xp3 = packdup(xv.w);
        ffma2(acc[0][0], w.x, xp0); ffma2(acc[0][1], w.y, xp0);
        ffma2(acc[1][0], w.x, xp1); ffma2(acc[1][1], w.y, xp1);
        ffma2(acc[2][0], w.x, xp2); ffma2(acc[2][1], w.y, xp2);
        ffma2(acc[3][0], w.x, xp3); ffma2(acc[3][1], w.y, xp3);
    }
    float4 av = __ldg((const float4*)&attS[tx * 4]);
    float4 dv = __ldg((const float4*)&attD[tx * 4]);
    #pragma unroll
    for (int i = 0; i < 4; ++i) {
        int nn = base + ty * 4 + i;
        float f0 = lo32(acc[i][0]), f1 = hi32(acc[i][0]);
        float f2 = lo32(acc[i][1]), f3 = hi32(acc[i][1]);
        if (nn < n) {
            __half2 p01 = __floats2half2_rn(f0, f1);
            __half2 p23 = __floats2half2_rn(f2, f3);
            uint2 u;
            u.x = reinterpret_cast<unsigned&>(p01);
            u.y = reinterpret_cast<unsigned&>(p23);
            *(uint2*)(g_h1h + (size_t)nn * F1 + tx * 4) = u;
        }
        float ps = f0 * av.x + f1 * av.y + f2 * av.z + f3 * av.w;
        float pd = f0 * dv.x + f1 * dv.y + f2 * dv.z + f3 * dv.w;
        #pragma unroll
        for (int o = 8; o > 0; o >>= 1) {
            ps += __shfl_xor_sync(0xffffffffu, ps, o);
            pd += __shfl_xor_sync(0xffffffffu, pd, o);
        }
        if ((tx & 15) == 0 && nn < n) {
            g_as1[2 * nn + (tx >> 4)] = ps * LOG2E;
            g_ad1[2 * nn + (tx >> 4)] = pd * LOG2E;
        }
    }
}

// ------- layer-1 gather: quad CSR + 2-stage software pipeline ------------------
__global__ void __launch_bounds__(256)
k_gather1(const float* __restrict__ bias1,
          const float* __restrict__ gamma,
          const float* __restrict__ beta, int n) {
    int node = (blockIdx.x * blockDim.x + threadIdx.x) >> 5;
    if (node >= n) return;
    int lane = threadIdx.x & 31;
    int h = lane >> 4;
    float2 ladp = *(const float2*)&g_ad1[2 * node];
    float lad = h ? ladp.y : ladp.x;
    float a0 = 0.f, a1 = 0.f, a2 = 0.f, a3 = 0.f, s = 0.f;
    float b0 = 0.f, b1 = 0.f, b2 = 0.f, b3 = 0.f, s2 = 0.f;
    // self-loop
    {
        float2 lasp = *(const float2*)&g_as1[2 * node];
        float wv = exp2f(lrelu((h ? lasp.y : lasp.x) + lad));
        uint2 r = *(const uint2*)(g_h1h + (size_t)node * F1 + 4 * lane);
        float2 fA = __half22float2(reinterpret_cast<__half2&>(r.x));
        float2 fB = __half22float2(reinterpret_cast<__half2&>(r.y));
        a0 += wv * fA.x; a1 += wv * fA.y; a2 += wv * fB.x; a3 += wv * fB.y; s += wv;
    }
    int e = g_off[node], endp = g_off[node + 1];
    if (e < endp) {
        // stage-0 prefetch
        int4 q = *(const int4*)&g_csr[e];
        float2 pA = *(const float2*)&g_as1[2 * q.x];
        float2 pB = *(const float2*)&g_as1[2 * q.y];
        float2 pC = *(const float2*)&g_as1[2 * q.z];
        float2 pD = *(const float2*)&g_as1[2 * q.w];
        uint2 rA = *(const uint2*)(g_h1h + (size_t)q.x * F1 + 4 * lane);
        uint2 rB = *(const uint2*)(g_h1h + (size_t)q.y * F1 + 4 * lane);
        uint2 rC = *(const uint2*)(g_h1h + (size_t)q.z * F1 + 4 * lane);
        uint2 rD = *(const uint2*)(g_h1h + (size_t)q.w * F1 + 4 * lane);
        for (;;) {
            int en = e + 4;
            bool more = en < endp;
            int ep = more ? en : e;   // final iter: redundant reload (discarded)
            // prefetch next quad
            int4 qn = *(const int4*)&g_csr[ep];
            float2 pA2 = *(const float2*)&g_as1[2 * qn.x];
            float2 pB2 = *(const float2*)&g_as1[2 * qn.y];
            float2 pC2 = *(const float2*)&g_as1[2 * qn.z];
            float2 pD2 = *(const float2*)&g_as1[2 * qn.w];
            uint2 rA2 = *(const uint2*)(g_h1h + (size_t)qn.x * F1 + 4 * lane);
            uint2 rB2 = *(const uint2*)(g_h1h + (size_t)qn.y * F1 + 4 * lane);
            uint2 rC2 = *(const uint2*)(g_h1h + (size_t)qn.z * F1 + 4 * lane);
            uint2 rD2 = *(const uint2*)(g_h1h + (size_t)qn.w * F1 + 4 * lane);
            // process current quad
            float wA = exp2f(lrelu((h ? pA.y : pA.x) + lad));
            float wB = exp2f(lrelu((h ? pB.y : pB.x) + lad));
            float wC = exp2f(lrelu((h ? pC.y : pC.x) + lad));
            float wD = exp2f(lrelu((h ? pD.y : pD.x) + lad));
            float2 f;
            f = __half22float2(reinterpret_cast<__half2&>(rA.x)); a0 += wA * f.x; a1 += wA * f.y;
            f = __half22float2(reinterpret_cast<__half2&>(rA.y)); a2 += wA * f.x; a3 += wA * f.y;
            f = __half22float2(reinterpret_cast<__half2&>(rB.x)); b0 += wB * f.x; b1 += wB * f.y;
            f = __half22float2(reinterpret_cast<__half2&>(rB.y)); b2 += wB * f.x; b3 += wB * f.y;
            f = __half22float2(reinterpret_cast<__half2&>(rC.x)); a0 += wC * f.x; a1 += wC * f.y;
            f = __half22float2(reinterpret_cast<__half2&>(rC.y)); a2 += wC * f.x; a3 += wC * f.y;
            f = __half22float2(reinterpret_cast<__half2&>(rD.x)); b0 += wD * f.x; b1 += wD * f.y;
            f = __half22float2(reinterpret_cast<__half2&>(rD.y)); b2 += wD * f.x; b3 += wD * f.y;
            s += wA + wC; s2 += wB + wD;
            if (!more) break;
            e = en;
            q = qn;
            pA = pA2; pB = pB2; pC = pC2; pD = pD2;
            rA = rA2; rB = rB2; rC = rC2; rD = rD2;
        }
    }
    a0 += b0; a1 += b1; a2 += b2; a3 += b3; s += s2;

    int c = 4 * lane;
    float r = 1.f / s;
    float4 bi = *(const float4*)&bias1[c];
    float v0 = a0 * r + bi.x;
    float v1 = a1 * r + bi.y;
    float v2 = a2 * r + bi.z;
    float v3 = a3 * r + bi.w;
    float tot = v0 + v1 + v2 + v3;
    #pragma unroll
    for (int o = 16; o > 0; o >>= 1) tot += __shfl_xor_sync(0xffffffffu, tot, o);
    float mu = tot * (1.f / 128.f);
    float d0 = v0 - mu, d1 = v1 - mu, d2 = v2 - mu, d3 = v3 - mu;
    float sq = d0 * d0 + d1 * d1 + d2 * d2 + d3 * d3;
    #pragma unroll
    for (int o = 16; o > 0; o >>= 1) sq += __shfl_xor_sync(0xffffffffu, sq, o);
    float inv = rsqrtf(sq * (1.f / 128.f) + 1e-5f);
    float4 gm = *(const float4*)&gamma[c];
    float4 bt = *(const float4*)&beta[c];
    float y0 = fmaxf(d0 * inv * gm.x + bt.x, 0.f);
    float y1 = fmaxf(d1 * inv * gm.y + bt.y, 0.f);
    float y2 = fmaxf(d2 * inv * gm.z + bt.z, 0.f);
    float y3 = fmaxf(d3 * inv * gm.w + bt.w, 0.f);
    {
        __half2 p01 = __floats2half2_rn(y0, y1);
        __half2 p23 = __floats2half2_rn(y2, y3);
        uint2 u;
        u.x = reinterpret_cast<unsigned&>(p01);
        u.y = reinterpret_cast<unsigned&>(p23);
        *(uint2*)(g_hlnh + (size_t)node * F1 + c) = u;
    }
    float4 ws = *(const float4*)&g_was2[c];
    float4 wd = *(const float4*)&g_wad2[c];
    float sa = y0 * ws.x + y1 * ws.y + y2 * ws.z + y3 * ws.w;
    float sd = y0 * wd.x + y1 * wd.y + y2 * wd.z + y3 * wd.w;
    #pragma unroll
    for (int o = 16; o > 0; o >>= 1) {
        sa += __shfl_xor_sync(0xffffffffu, sa, o);
        sd += __shfl_xor_sync(0xffffffffu, sd, o);
    }
    if (lane == 0) { g_as2[node] = sa * LOG2E; g_ad2[node] = sd * LOG2E; }
}

// ---------------- layer-2 projection: h2(fp16) = hln(fp16) @ W2 ----------------
__global__ void k4_proj(const float* __restrict__ W2, int n) {
    __shared__ __align__(16) float Ws[F1 * OUTC];
    __shared__ __half2 xsT[F1 / 2][33];
    int t = threadIdx.x;                                // 128
    for (int i = t; i < F1 * OUTC; i += 128) Ws[i] = W2[i];
    int base = blockIdx.x * 32;
    #pragma unroll
    for (int i = 0; i < 16; ++i) {
        int idx = t + i * 128;
        int node = idx >> 6, kk = idx & 63;
        int nn = base + node;
        xsT[kk][node] = (nn < n) ? ((const __half2*)g_hlnh)[(size_t)nn * 64 + kk]
                                 : __float2half2_rn(0.f);
    }
    __syncthreads();
    int tx = t & 15;
    int ty = t >> 4;
    unsigned long long acc[4][2] = {};
    #pragma unroll 4
    for (int kk = 0; kk < 64; ++kk) {
        ulonglong2 wA = *(const ulonglong2*)&Ws[(2 * kk)     * OUTC + tx * 4];
        ulonglong2 wB = *(const ulonglong2*)&Ws[(2 * kk + 1) * OUTC + tx * 4];
        #pragma unroll
        for (int i = 0; i < 4; ++i) {
            float2 f = __half22float2(xsT[kk][ty * 4 + i]);
            unsigned long long xp0 = packdup(f.x), xp1 = packdup(f.y);
            ffma2(acc[i][0], wA.x, xp0); ffma2(acc[i][0], wB.x, xp1);
            ffma2(acc[i][1], wA.y, xp0); ffma2(acc[i][1], wB.y, xp1);
        }
    }
    #pragma unroll
    for (int i = 0; i < 4; ++i) {
        int nn = base + ty * 4 + i;
        if (nn >= n) continue;
        __half2 p01 = __floats2half2_rn(lo32(acc[i][0]), hi32(acc[i][0]));
        __half2 p23 = __floats2half2_rn(lo32(acc[i][1]), hi32(acc[i][1]));
        uint2 u;
        u.x = reinterpret_cast<unsigned&>(p01);
        u.y = reinterpret_cast<unsigned&>(p23);
        *(uint2*)(g_h2h + (size_t)nn * OUTC + tx * 4) = u;
    }
}

// ------- layer-2 gather: quad CSR + 2-stage software pipeline ------------------
__global__ void __launch_bounds__(256)
k_gather2(float* __restrict__ out, const float* __restrict__ bias2, int n) {
    int node = (blockIdx.x * blockDim.x + threadIdx.x) >> 5;
    if (node >= n) return;
    int lane = threadIdx.x & 31;
    float lad = g_ad2[node];
    float ax = 0.f, ay = 0.f, ssum = 0.f;
    float bx = 0.f, by = 0.f, tsum = 0.f;
    {
        float w = exp2f(lrelu(g_as2[node] + lad));
        float2 f = __half22float2(((const __half2*)(g_h2h + (size_t)node * OUTC))[lane]);
        ax += w * f.x; ay += w * f.y; ssum += w;
    }
    int e = g_off[node], endp = g_off[node + 1];
    if (e < endp) {
        int4 q = *(const int4*)&g_csr[e];
        float eA = g_as2[q.x], eB = g_as2[q.y], eC = g_as2[q.z], eD = g_as2[q.w];
        __half2 rA = ((const __half2*)(g_h2h + (size_t)q.x * OUTC))[lane];
        __half2 rB = ((const __half2*)(g_h2h + (size_t)q.y * OUTC))[lane];
        __half2 rC = ((const __half2*)(g_h2h + (size_t)q.z * OUTC))[lane];
        __half2 rD = ((const __half2*)(g_h2h + (size_t)q.w * OUTC))[lane];
        for (;;) {
            int en = e + 4;
            bool more = en < endp;
            int ep = more ? en : e;
            int4 qn = *(const int4*)&g_csr[ep];
            float eA2 = g_as2[qn.x], eB2 = g_as2[qn.y], eC2 = g_as2[qn.z], eD2 = g_as2[qn.w];
            __half2 rA2 = ((const __half2*)(g_h2h + (size_t)qn.x * OUTC))[lane];
            __half2 rB2 = ((const __half2*)(g_h2h + (size_t)qn.y * OUTC))[lane];
            __half2 rC2 = ((const __half2*)(g_h2h + (size_t)qn.z * OUTC))[lane];
            __half2 rD2 = ((const __half2*)(g_h2h + (size_t)qn.w * OUTC))[lane];
            float wA = exp2f(lrelu(eA + lad));
            float wB = exp2f(lrelu(eB + lad));
            float wC = exp2f(lrelu(eC + lad));
            float wD = exp2f(lrelu(eD + lad));
            float2 f;
            f = __half22float2(rA); ax += wA * f.x; ay += wA * f.y;
            f = __half22float2(rB); bx += wB * f.x; by += wB * f.y;
            f = __half22float2(rC); ax += wC * f.x; ay += wC * f.y;
            f = __half22float2(rD); bx += wD * f.x; by += wD * f.y;
            ssum += wA + wC; tsum += wB + wD;
            if (!more) break;
            e = en;
            eA = eA2; eB = eB2; eC = eC2; eD = eD2;
            rA = rA2; rB = rB2; rC = rC2; rD = rD2;
        }
    }
    ax += bx; ay += by; ssum += tsum;
    float r = 1.f / ssum;
    float2 o;
    o.x = ax * r + bias2[2 * lane];
    o.y = ay * r + bias2[2 * lane + 1];
    ((float2*)out)[(size_t)node * 32 + lane] = o;
}

// ---------------- launcher -----------------------------------------------------
extern "C" void kernel_launch(void* const* d_in, const int* in_sizes, int n_in,
                              void* d_out, int out_size) {
    const float* x     = (const float*)d_in[0];
    const int*   ei    = (const int*)  d_in[1];
    const float* W1    = (const float*)d_in[2];
    const float* as1   = (const float*)d_in[3];
    const float* ad1   = (const float*)d_in[4];
    const float* b1    = (const float*)d_in[5];
    const float* gamma = (const float*)d_in[6];
    const float* beta  = (const float*)d_in[7];
    const float* W2    = (const float*)d_in[8];
    const float* as2   = (const float*)d_in[9];
    const float* ad2   = (const float*)d_in[10];
    const float* b2    = (const float*)d_in[11];
    float* out = (float*)d_out;

    int n = in_sizes[0] / IN_DIM;
    int E = in_sizes[1] / 2;
    const int* srcp = ei;
    const int* dstp = ei + E;

    k_csr<<<CSR_BLOCKS, CSR_THREADS>>>(srcp, dstp, E, n);          // 1
    k_fold2<<<1, 128>>>(W2, as2, ad2, n);                          // 2
    k1_proj<<<(n + 31) / 32, 256>>>(x, W1, as1, ad1, n);           // 3
    k_gather1<<<(n + 7) / 8, 256>>>(b1, gamma, beta, n);           // 4 <- profiled
    k4_proj<<<(n + 31) / 32, 128>>>(W2, n);                        // 5
    k_gather2<<<(n + 7) / 8, 256>>>(out, b2, n);                   // 6
}

// round 7
// speedup vs baseline: 1.0415x; 1.0415x over previous
#include <cuda_runtime.h>
#include <cuda_fp16.h>

#define N_NODES 100000
#define E_EDGES 1600000
#define IN_DIM 32
#define HID 64
#define NHEADS 2
#define F1 128   // NHEADS*HID
#define OUTC 64
#define LOG2E 1.4426950408889634f

#define CSR_BLOCKS 512
#define CSR_THREADS 256

// ---------------- scratch (device globals; no allocation allowed) ------------
__device__ __align__(16) __half g_h1h [(size_t)(N_NODES + 1) * F1];
__device__ __align__(16) __half g_hlnh[(size_t)N_NODES * F1];
__device__ __align__(16) __half g_h2h [(size_t)(N_NODES + 1) * OUTC];
__device__ __align__(16) float g_as1[(N_NODES + 1) * NHEADS];
__device__ __align__(16) float g_ad1[(N_NODES + 1) * NHEADS];
__device__ float g_as2[N_NODES + 1];
__device__ float g_ad2[N_NODES + 1];
__device__ int   g_deg[N_NODES];
__device__ int   g_off[N_NODES + 1];
__device__ int   g_cur[N_NODES];
__device__ __align__(16) int g_csr[E_EDGES + 3 * N_NODES + 8];
__device__ int   g_bsum[CSR_BLOCKS];
__device__ int   g_bscan[CSR_BLOCKS];
__device__ __align__(16) float g_was2[F1];
__device__ __align__(16) float g_wad2[F1];
__device__ int   g_bar_count;
__device__ int   g_bar_gen;

__device__ __forceinline__ float lrelu(float v) { return v > 0.f ? v : 0.2f * v; }

// ---- packed fp32x2 helpers ----------------------------------------------------
__device__ __forceinline__ unsigned long long packdup(float a) {
    unsigned long long r;
    asm("mov.b64 %0, {%1, %1};" : "=l"(r) : "f"(a));
    return r;
}
__device__ __forceinline__ unsigned long long f2u64(float2 f) {
    unsigned long long r;
    asm("mov.b64 %0, {%1, %2};" : "=l"(r) : "f"(f.x), "f"(f.y));
    return r;
}
__device__ __forceinline__ void ffma2(unsigned long long& acc,
                                      unsigned long long a, unsigned long long b) {
    asm("fma.rn.f32x2 %0, %1, %2, %0;" : "+l"(acc) : "l"(a), "l"(b));
}
__device__ __forceinline__ float lo32(unsigned long long v) {
    return __uint_as_float((unsigned)(v & 0xffffffffull));
}
__device__ __forceinline__ float hi32(unsigned long long v) {
    return __uint_as_float((unsigned)(v >> 32));
}
__device__ __forceinline__ float2 h2f2(unsigned h) {
    return __half22float2(reinterpret_cast<__half2&>(h));
}

// ---- software grid barrier ----------------------------------------------------
__device__ __forceinline__ void gsync() {
    __syncthreads();
    __threadfence();
    if (threadIdx.x == 0) {
        int gen = *(volatile int*)&g_bar_gen;
        if (atomicAdd(&g_bar_count, 1) == CSR_BLOCKS - 1) {
            g_bar_count = 0;
            __threadfence();
            *(volatile int*)&g_bar_gen = gen + 1;
        } else {
            while (*(volatile int*)&g_bar_gen == gen) { }
        }
        __threadfence();
    }
    __syncthreads();
}

// ------- fused CSR build: zero + degree + scan(pad4) + pad-fill + scatter ------
__global__ void __launch_bounds__(CSR_THREADS, 8)
k_csr(const int* __restrict__ src, const int* __restrict__ dst, int E, int n) {
    const int T = CSR_BLOCKS * CSR_THREADS;
    int t = threadIdx.x;
    int gt = blockIdx.x * CSR_THREADS + t;
    int lane = t & 31, w = t >> 5;
    __shared__ int wsum[8];

    for (int i = gt; i < n; i += T) g_deg[i] = 0;
    gsync();
    int E4 = E >> 2;
    for (int i = gt; i < E4; i += T) {
        int4 d4 = ((const int4*)dst)[i];
        atomicAdd(&g_deg[d4.x], 1);
        atomicAdd(&g_deg[d4.y], 1);
        atomicAdd(&g_deg[d4.z], 1);
        atomicAdd(&g_deg[d4.w], 1);
    }
    for (int e = E4 * 4 + gt; e < E; e += T) atomicAdd(&g_deg[dst[e]], 1);
    gsync();
    int C = (n + T - 1) / T;
    int b0 = gt * C;
    int s = 0;
    for (int i = 0; i < C; ++i) {
        int idx = b0 + i;
        if (idx < n) s += (g_deg[idx] + 3) & ~3;
    }
    int incl = s;
    #pragma unroll
    for (int o = 1; o < 32; o <<= 1) {
        int xv = __shfl_up_sync(0xffffffffu, incl, o);
        if (lane >= o) incl += xv;
    }
    if (lane == 31) wsum[w] = incl;
    __syncthreads();
    if (t < 8) {
        int xv = wsum[t];
        #pragma unroll
        for (int o = 1; o < 8; o <<= 1) {
            int y = __shfl_up_sync(0xffu, xv, o);
            if (t >= o) xv += y;
        }
        wsum[t] = xv;
    }
    __syncthreads();
    int excl = incl - s + (w > 0 ? wsum[w - 1] : 0);
    if (t == CSR_THREADS - 1) g_bsum[blockIdx.x] = excl + s;
    gsync();
    if (blockIdx.x == 0) {
        int a0 = g_bsum[2 * t], a1 = g_bsum[2 * t + 1];
        int ss = a0 + a1;
        int in2 = ss;
        #pragma unroll
        for (int o = 1; o < 32; o <<= 1) {
            int xv = __shfl_up_sync(0xffffffffu, in2, o);
            if (lane >= o) in2 += xv;
        }
        if (lane == 31) wsum[w] = in2;
        __syncthreads();
        if (t < 8) {
            int xv = wsum[t];
            #pragma unroll
            for (int o = 1; o < 8; o <<= 1) {
                int y = __shfl_up_sync(0xffu, xv, o);
                if (t >= o) xv += y;
            }
            wsum[t] = xv;
        }
        __syncthreads();
        int ex2 = in2 - ss + (w > 0 ? wsum[w - 1] : 0);
        g_bscan[2 * t]     = ex2;
        g_bscan[2 * t + 1] = ex2 + a0;
    }
    gsync();
    int off = excl + g_bscan[blockIdx.x];
    for (int i = 0; i < C; ++i) {
        int idx = b0 + i;
        if (idx < n) {
            int d = g_deg[idx];
            int p = (d + 3) & ~3;
            g_off[idx] = off;
            g_cur[idx] = off;
            for (int j = d; j < p; ++j) g_csr[off + j] = n;  // dummy
            if (idx == n - 1) g_off[n] = off + p;
            off += p;
        }
    }
    gsync();
    for (int i = gt; i < E4; i += T) {
        int4 s4 = ((const int4*)src)[i];
        int4 d4 = ((const int4*)dst)[i];
        g_csr[atomicAdd(&g_cur[d4.x], 1)] = s4.x;
        g_csr[atomicAdd(&g_cur[d4.y], 1)] = s4.y;
        g_csr[atomicAdd(&g_cur[d4.z], 1)] = s4.z;
        g_csr[atomicAdd(&g_cur[d4.w], 1)] = s4.w;
    }
    for (int e = E4 * 4 + gt; e < E; e += T) {
        g_csr[atomicAdd(&g_cur[dst[e]], 1)] = src[e];
    }
}

// ------- layer-2 attention fold + dummy-node init ------------------------------
__global__ void k_fold2(const float* __restrict__ W2,
                        const float* __restrict__ as2, const float* __restrict__ ad2, int n) {
    int t = threadIdx.x;  // 128
    float s = 0.f, d = 0.f;
    for (int c = 0; c < OUTC; ++c) {
        float w = W2[t * OUTC + c];
        s += w * as2[c];
        d += w * ad2[c];
    }
    g_was2[t] = s;
    g_wad2[t] = d;
    if (t < 2) { g_as1[2 * n + t] = -1e30f; g_ad1[2 * n + t] = 0.f; }
    if (t == 0) { g_as2[n] = -1e30f; g_ad2[n] = 0.f; }
    g_h1h[(size_t)n * F1 + t] = __float2half(0.f);
    if (t < OUTC) g_h2h[(size_t)n * OUTC + t] = __float2half(0.f);
}

// ---------------- layer-1 projection + logits (prescaled by log2e) -------------
__global__ void k1_proj(const float* __restrict__ x, const float* __restrict__ W1,
                        const float* __restrict__ attS, const float* __restrict__ attD, int n) {
    __shared__ __align__(16) float Ws[IN_DIM * F1];
    __shared__ __align__(16) float xsT[IN_DIM][36];
    int t = threadIdx.x;                                // 256
    for (int i = t; i < IN_DIM * F1; i += 256) Ws[i] = W1[i];
    int base = blockIdx.x * 32;
    #pragma unroll
    for (int i = 0; i < 4; ++i) {
        int idx = t + i * 256;
        int node = idx >> 5, k = idx & 31;
        int nn = base + node;
        xsT[k][node] = (nn < n) ? x[(size_t)nn * IN_DIM + k] : 0.f;
    }
    __syncthreads();
    int tx = t & 31;
    int ty = t >> 5;
    unsigned long long acc[4][2] = {};
    #pragma unroll
    for (int k = 0; k < IN_DIM; ++k) {
        ulonglong2 w = *(const ulonglong2*)&Ws[k * F1 + tx * 4];
        float4 xv = *(const float4*)&xsT[k][ty * 4];
        unsigned long long xp0 = packdup(xv.x), xp1 = packdup(xv.y);
        unsigned long long xp2 = packdup(xv.z), xp3 = packdup(xv.w);
        ffma2(acc[0][0], w.x, xp0); ffma2(acc[0][1], w.y, xp0);
        ffma2(acc[1][0], w.x, xp1); ffma2(acc[1][1], w.y, xp1);
        ffma2(acc[2][0], w.x, xp2); ffma2(acc[2][1], w.y, xp2);
        ffma2(acc[3][0], w.x, xp3); ffma2(acc[3][1], w.y, xp3);
    }
    float4 av = __ldg((const float4*)&attS[tx * 4]);
    float4 dv = __ldg((const float4*)&attD[tx * 4]);
    #pragma unroll
    for (int i = 0; i < 4; ++i) {
        int nn = base + ty * 4 + i;
        float f0 = lo32(acc[i][0]), f1 = hi32(acc[i][0]);
        float f2 = lo32(acc[i][1]), f3 = hi32(acc[i][1]);
        if (nn < n) {
            __half2 p01 = __floats2half2_rn(f0, f1);
            __half2 p23 = __floats2half2_rn(f2, f3);
            uint2 u;
            u.x = reinterpret_cast<unsigned&>(p01);
            u.y = reinterpret_cast<unsigned&>(p23);
            *(uint2*)(g_h1h + (size_t)nn * F1 + tx * 4) = u;
        }
        float ps = f0 * av.x + f1 * av.y + f2 * av.z + f3 * av.w;
        float pd = f0 * dv.x + f1 * dv.y + f2 * dv.z + f3 * dv.w;
        #pragma unroll
        for (int o = 8; o > 0; o >>= 1) {
            ps += __shfl_xor_sync(0xffffffffu, ps, o);
            pd += __shfl_xor_sync(0xffffffffu, pd, o);
        }
        if ((tx & 15) == 0 && nn < n) {
            g_as1[2 * nn + (tx >> 4)] = ps * LOG2E;
            g_ad1[2 * nn + (tx >> 4)] = pd * LOG2E;
        }
    }
}

// ------- layer-1 gather: padded dual-unroll + FFMA2 accumulate -----------------
__global__ void __launch_bounds__(128)
k_gather1(const float* __restrict__ bias1,
          const float* __restrict__ gamma,
          const float* __restrict__ beta, int n) {
    int node = (blockIdx.x * blockDim.x + threadIdx.x) >> 5;
    if (node >= n) return;
    int lane = threadIdx.x & 31;
    int h = lane >> 4;
    float2 ladp = *(const float2*)&g_ad1[2 * node];
    float lad = h ? ladp.y : ladp.x;
    unsigned long long accA0 = 0, accA1 = 0, accB0 = 0, accB1 = 0;
    float s = 0.f, s2 = 0.f;
    // self-loop
    {
        float2 lasp = *(const float2*)&g_as1[2 * node];
        float wv = exp2f(lrelu((h ? lasp.y : lasp.x) + lad));
        uint2 r = *(const uint2*)(g_h1h + (size_t)node * F1 + 4 * lane);
        unsigned long long wd = packdup(wv);
        ffma2(accA0, wd, f2u64(h2f2(r.x)));
        ffma2(accA1, wd, f2u64(h2f2(r.y)));
        s += wv;
    }
    int e = g_off[node], endp = g_off[node + 1];   // padded: multiple of 2
    for (; e < endp; e += 2) {
        int2 q = *(const int2*)&g_csr[e];
        float2 pA = *(const float2*)&g_as1[2 * q.x];
        float2 pB = *(const float2*)&g_as1[2 * q.y];
        uint2 rA = *(const uint2*)(g_h1h + (size_t)q.x * F1 + 4 * lane);
        uint2 rB = *(const uint2*)(g_h1h + (size_t)q.y * F1 + 4 * lane);
        float wA = exp2f(lrelu((h ? pA.y : pA.x) + lad));
        float wB = exp2f(lrelu((h ? pB.y : pB.x) + lad));
        unsigned long long wAd = packdup(wA), wBd = packdup(wB);
        ffma2(accA0, wAd, f2u64(h2f2(rA.x)));
        ffma2(accA1, wAd, f2u64(h2f2(rA.y)));
        ffma2(accB0, wBd, f2u64(h2f2(rB.x)));
        ffma2(accB1, wBd, f2u64(h2f2(rB.y)));
        s += wA; s2 += wB;
    }
    s += s2;
    float a0 = lo32(accA0) + lo32(accB0);
    float a1 = hi32(accA0) + hi32(accB0);
    float a2 = lo32(accA1) + lo32(accB1);
    float a3 = hi32(accA1) + hi32(accB1);

    int c = 4 * lane;
    float r = 1.f / s;
    float4 bi = *(const float4*)&bias1[c];
    float v0 = a0 * r + bi.x;
    float v1 = a1 * r + bi.y;
    float v2 = a2 * r + bi.z;
    float v3 = a3 * r + bi.w;
    float tot = v0 + v1 + v2 + v3;
    #pragma unroll
    for (int o = 16; o > 0; o >>= 1) tot += __shfl_xor_sync(0xffffffffu, tot, o);
    float mu = tot * (1.f / 128.f);
    float d0 = v0 - mu, d1 = v1 - mu, d2 = v2 - mu, d3 = v3 - mu;
    float sq = d0 * d0 + d1 * d1 + d2 * d2 + d3 * d3;
    #pragma unroll
    for (int o = 16; o > 0; o >>= 1) sq += __shfl_xor_sync(0xffffffffu, sq, o);
    float inv = rsqrtf(sq * (1.f / 128.f) + 1e-5f);
    float4 gm = *(const float4*)&gamma[c];
    float4 bt = *(const float4*)&beta[c];
    float y0 = fmaxf(d0 * inv * gm.x + bt.x, 0.f);
    float y1 = fmaxf(d1 * inv * gm.y + bt.y, 0.f);
    float y2 = fmaxf(d2 * inv * gm.z + bt.z, 0.f);
    float y3 = fmaxf(d3 * inv * gm.w + bt.w, 0.f);
    {
        __half2 p01 = __floats2half2_rn(y0, y1);
        __half2 p23 = __floats2half2_rn(y2, y3);
        uint2 u;
        u.x = reinterpret_cast<unsigned&>(p01);
        u.y = reinterpret_cast<unsigned&>(p23);
        *(uint2*)(g_hlnh + (size_t)node * F1 + c) = u;
    }
    float4 ws = *(const float4*)&g_was2[c];
    float4 wd = *(const float4*)&g_wad2[c];
    float sa = y0 * ws.x + y1 * ws.y + y2 * ws.z + y3 * ws.w;
    float sd = y0 * wd.x + y1 * wd.y + y2 * wd.z + y3 * wd.w;
    #pragma unroll
    for (int o = 16; o > 0; o >>= 1) {
        sa += __shfl_xor_sync(0xffffffffu, sa, o);
        sd += __shfl_xor_sync(0xffffffffu, sd, o);
    }
    if (lane == 0) { g_as2[node] = sa * LOG2E; g_ad2[node] = sd * LOG2E; }
}

// ---------------- layer-2 projection: 64 nodes/block, 256 threads --------------
__global__ void __launch_bounds__(256)
k4_proj(const float* __restrict__ W2, int n) {
    __shared__ __align__(16) float Ws[F1 * OUTC];       // 32 KB
    __shared__ __half2 xsT[F1 / 2][65];                 // 64 kk x 64 nodes (+pad)
    int t = threadIdx.x;                                // 256
    for (int i = t; i < F1 * OUTC; i += 256) Ws[i] = W2[i];
    int base = blockIdx.x * 64;
    #pragma unroll
    for (int i = 0; i < 16; ++i) {
        int idx = t + i * 256;
        int node = idx >> 6, kk = idx & 63;
        int nn = base + node;
        xsT[kk][node] = (nn < n) ? ((const __half2*)g_hlnh)[(size_t)nn * 64 + kk]
                                 : __float2half2_rn(0.f);
    }
    __syncthreads();
    int tx = t & 15;        // cols tx*4 .. +3
    int ty = t >> 4;        // nodes ty*4 .. +3 (0..15)
    unsigned long long acc[4][2] = {};
    #pragma unroll 4
    for (int kk = 0; kk < 64; ++kk) {
        ulonglong2 wA = *(const ulonglong2*)&Ws[(2 * kk)     * OUTC + tx * 4];
        ulonglong2 wB = *(const ulonglong2*)&Ws[(2 * kk + 1) * OUTC + tx * 4];
        #pragma unroll
        for (int i = 0; i < 4; ++i) {
            float2 f = __half22float2(xsT[kk][ty * 4 + i]);
            unsigned long long xp0 = packdup(f.x), xp1 = packdup(f.y);
            ffma2(acc[i][0], wA.x, xp0); ffma2(acc[i][0], wB.x, xp1);
            ffma2(acc[i][1], wA.y, xp0); ffma2(acc[i][1], wB.y, xp1);
        }
    }
    #pragma unroll
    for (int i = 0; i < 4; ++i) {
        int nn = base + ty * 4 + i;
        if (nn >= n) continue;
        __half2 p01 = __floats2half2_rn(lo32(acc[i][0]), hi32(acc[i][0]));
        __half2 p23 = __floats2half2_rn(lo32(acc[i][1]), hi32(acc[i][1]));
        uint2 u;
        u.x = reinterpret_cast<unsigned&>(p01);
        u.y = reinterpret_cast<unsigned&>(p23);
        *(uint2*)(g_h2h + (size_t)nn * OUTC + tx * 4) = u;
    }
}

// ------- layer-2 gather: padded dual-unroll + FFMA2 ----------------------------
__global__ void __launch_bounds__(128)
k_gather2(float* __restrict__ out, const float* __restrict__ bias2, int n) {
    int node = (blockIdx.x * blockDim.x + threadIdx.x) >> 5;
    if (node >= n) return;
    int lane = threadIdx.x & 31;
    float lad = g_ad2[node];
    unsigned long long accA = 0, accB = 0;
    float ssum = 0.f, tsum = 0.f;
    {
        float w = exp2f(lrelu(g_as2[node] + lad));
        unsigned r = ((const unsigned*)(g_h2h + (size_t)node * OUTC))[lane];
        ffma2(accA, packdup(w), f2u64(h2f2(r)));
        ssum += w;
    }
    int e = g_off[node], endp = g_off[node + 1];
    for (; e < endp; e += 2) {
        int2 q = *(const int2*)&g_csr[e];
        float eA = g_as2[q.x], eB = g_as2[q.y];
        unsigned rA = ((const unsigned*)(g_h2h + (size_t)q.x * OUTC))[lane];
        unsigned rB = ((const unsigned*)(g_h2h + (size_t)q.y * OUTC))[lane];
        float wA = exp2f(lrelu(eA + lad));
        float wB = exp2f(lrelu(eB + lad));
        ffma2(accA, packdup(wA), f2u64(h2f2(rA)));
        ffma2(accB, packdup(wB), f2u64(h2f2(rB)));
        ssum += wA; tsum += wB;
    }
    ssum += tsum;
    float ax = lo32(accA) + lo32(accB);
    float ay = hi32(accA) + hi32(accB);
    float r = 1.f / ssum;
    float2 o;
    o.x = ax * r + bias2[2 * lane];
    o.y = ay * r + bias2[2 * lane + 1];
    ((float2*)out)[(size_t)node * 32 + lane] = o;
}

// ---------------- launcher -----------------------------------------------------
extern "C" void kernel_launch(void* const* d_in, const int* in_sizes, int n_in,
                              void* d_out, int out_size) {
    const float* x     = (const float*)d_in[0];
    const int*   ei    = (const int*)  d_in[1];
    const float* W1    = (const float*)d_in[2];
    const float* as1   = (const float*)d_in[3];
    const float* ad1   = (const float*)d_in[4];
    const float* b1    = (const float*)d_in[5];
    const float* gamma = (const float*)d_in[6];
    const float* beta  = (const float*)d_in[7];
    const float* W2    = (const float*)d_in[8];
    const float* as2   = (const float*)d_in[9];
    const float* ad2   = (const float*)d_in[10];
    const float* b2    = (const float*)d_in[11];
    float* out = (float*)d_out;

    int n = in_sizes[0] / IN_DIM;
    int E = in_sizes[1] / 2;
    const int* srcp = ei;
    const int* dstp = ei + E;

    k_csr<<<CSR_BLOCKS, CSR_THREADS>>>(srcp, dstp, E, n);          // 1
    k_fold2<<<1, 128>>>(W2, as2, ad2, n);                          // 2
    k1_proj<<<(n + 31) / 32, 256>>>(x, W1, as1, ad1, n);           // 3
    k_gather1<<<(n + 3) / 4, 128>>>(b1, gamma, beta, n);           // 4 <- profiled
    k4_proj<<<(n + 63) / 64, 256>>>(W2, n);                        // 5
    k_gather2<<<(n + 3) / 4, 128>>>(out, b2, n);                   // 6
}

// round 8
// speedup vs baseline: 1.1522x; 1.1063x over previous
#include <cuda_runtime.h>
#include <cuda_fp16.h>

#define N_NODES 100000
#define E_EDGES 1600000
#define IN_DIM 32
#define HID 64
#define NHEADS 2
#define F1 128   // NHEADS*HID
#define OUTC 64
#define LOG2E 1.4426950408889634f

#define CSR_BLOCKS 512
#define CSR_THREADS 256

// ---------------- scratch (device globals; no allocation allowed) ------------
__device__ __align__(16) __half g_h1h [(size_t)(N_NODES + 1) * F1];
__device__ __align__(16) __half g_hlnh[(size_t)N_NODES * F1];
__device__ __align__(16) __half g_h2h [(size_t)(N_NODES + 1) * OUTC];
__device__ __align__(16) float g_as1[(N_NODES + 1) * NHEADS];
__device__ __align__(16) float g_ad1[(N_NODES + 1) * NHEADS];
__device__ float g_as2[N_NODES + 1];
__device__ float g_ad2[N_NODES + 1];
__device__ int   g_deg[N_NODES];
__device__ int   g_off[N_NODES + 1];
__device__ int   g_cur[N_NODES];
__device__ __align__(16) int g_csr[E_EDGES + 3 * N_NODES + 8];
__device__ int   g_bsum[CSR_BLOCKS];
__device__ int   g_bscan[CSR_BLOCKS];
__device__ __align__(16) float g_was2[F1];
__device__ __align__(16) float g_wad2[F1];
__device__ int   g_bar_count;
__device__ int   g_bar_gen;

__device__ __forceinline__ float lrelu(float v) { return v > 0.f ? v : 0.2f * v; }

// ---- packed fp32x2 helpers ----------------------------------------------------
__device__ __forceinline__ unsigned long long packdup(float a) {
    unsigned long long r;
    asm("mov.b64 %0, {%1, %1};" : "=l"(r) : "f"(a));
    return r;
}
__device__ __forceinline__ void ffma2(unsigned long long& acc,
                                      unsigned long long a, unsigned long long b) {
    asm("fma.rn.f32x2 %0, %1, %2, %0;" : "+l"(acc) : "l"(a), "l"(b));
}
__device__ __forceinline__ float lo32(unsigned long long v) {
    return __uint_as_float((unsigned)(v & 0xffffffffull));
}
__device__ __forceinline__ float hi32(unsigned long long v) {
    return __uint_as_float((unsigned)(v >> 32));
}
__device__ __forceinline__ float2 h2f2(unsigned h) {
    return __half22float2(reinterpret_cast<__half2&>(h));
}

// ---- software grid barrier ----------------------------------------------------
__device__ __forceinline__ void gsync() {
    __syncthreads();
    __threadfence();
    if (threadIdx.x == 0) {
        int gen = *(volatile int*)&g_bar_gen;
        if (atomicAdd(&g_bar_count, 1) == CSR_BLOCKS - 1) {
            g_bar_count = 0;
            __threadfence();
            *(volatile int*)&g_bar_gen = gen + 1;
        } else {
            while (*(volatile int*)&g_bar_gen == gen) { }
        }
        __threadfence();
    }
    __syncthreads();
}

// ------- fused CSR build: zero + degree + scan(pad4) + pad-fill + scatter ------
__global__ void __launch_bounds__(CSR_THREADS, 8)
k_csr(const int* __restrict__ src, const int* __restrict__ dst, int E, int n) {
    const int T = CSR_BLOCKS * CSR_THREADS;
    int t = threadIdx.x;
    int gt = blockIdx.x * CSR_THREADS + t;
    int lane = t & 31, w = t >> 5;
    __shared__ int wsum[8];

    for (int i = gt; i < n; i += T) g_deg[i] = 0;
    gsync();
    int E4 = E >> 2;
    for (int i = gt; i < E4; i += T) {
        int4 d4 = ((const int4*)dst)[i];
        atomicAdd(&g_deg[d4.x], 1);
        atomicAdd(&g_deg[d4.y], 1);
        atomicAdd(&g_deg[d4.z], 1);
        atomicAdd(&g_deg[d4.w], 1);
    }
    for (int e = E4 * 4 + gt; e < E; e += T) atomicAdd(&g_deg[dst[e]], 1);
    gsync();
    int C = (n + T - 1) / T;
    int b0 = gt * C;
    int s = 0;
    for (int i = 0; i < C; ++i) {
        int idx = b0 + i;
        if (idx < n) s += (g_deg[idx] + 3) & ~3;
    }
    int incl = s;
    #pragma unroll
    for (int o = 1; o < 32; o <<= 1) {
        int xv = __shfl_up_sync(0xffffffffu, incl, o);
        if (lane >= o) incl += xv;
    }
    if (lane == 31) wsum[w] = incl;
    __syncthreads();
    if (t < 8) {
        int xv = wsum[t];
        #pragma unroll
        for (int o = 1; o < 8; o <<= 1) {
            int y = __shfl_up_sync(0xffu, xv, o);
            if (t >= o) xv += y;
        }
        wsum[t] = xv;
    }
    __syncthreads();
    int excl = incl - s + (w > 0 ? wsum[w - 1] : 0);
    if (t == CSR_THREADS - 1) g_bsum[blockIdx.x] = excl + s;
    gsync();
    if (blockIdx.x == 0) {
        int a0 = g_bsum[2 * t], a1 = g_bsum[2 * t + 1];
        int ss = a0 + a1;
        int in2 = ss;
        #pragma unroll
        for (int o = 1; o < 32; o <<= 1) {
            int xv = __shfl_up_sync(0xffffffffu, in2, o);
            if (lane >= o) in2 += xv;
        }
        if (lane == 31) wsum[w] = in2;
        __syncthreads();
        if (t < 8) {
            int xv = wsum[t];
            #pragma unroll
            for (int o = 1; o < 8; o <<= 1) {
                int y = __shfl_up_sync(0xffu, xv, o);
                if (t >= o) xv += y;
            }
            wsum[t] = xv;
        }
        __syncthreads();
        int ex2 = in2 - ss + (w > 0 ? wsum[w - 1] : 0);
        g_bscan[2 * t]     = ex2;
        g_bscan[2 * t + 1] = ex2 + a0;
    }
    gsync();
    int off = excl + g_bscan[blockIdx.x];
    for (int i = 0; i < C; ++i) {
        int idx = b0 + i;
        if (idx < n) {
            int d = g_deg[idx];
            int p = (d + 3) & ~3;
            g_off[idx] = off;
            g_cur[idx] = off;
            for (int j = d; j < p; ++j) g_csr[off + j] = n;  // dummy
            if (idx == n - 1) g_off[n] = off + p;
            off += p;
        }
    }
    gsync();
    for (int i = gt; i < E4; i += T) {
        int4 s4 = ((const int4*)src)[i];
        int4 d4 = ((const int4*)dst)[i];
        g_csr[atomicAdd(&g_cur[d4.x], 1)] = s4.x;
        g_csr[atomicAdd(&g_cur[d4.y], 1)] = s4.y;
        g_csr[atomicAdd(&g_cur[d4.z], 1)] = s4.z;
        g_csr[atomicAdd(&g_cur[d4.w], 1)] = s4.w;
    }
    for (int e = E4 * 4 + gt; e < E; e += T) {
        g_csr[atomicAdd(&g_cur[dst[e]], 1)] = src[e];
    }
}

// ------- layer-2 attention fold + dummy-node init ------------------------------
__global__ void k_fold2(const float* __restrict__ W2,
                        const float* __restrict__ as2, const float* __restrict__ ad2, int n) {
    int t = threadIdx.x;  // 128
    float s = 0.f, d = 0.f;
    for (int c = 0; c < OUTC; ++c) {
        float w = W2[t * OUTC + c];
        s += w * as2[c];
        d += w * ad2[c];
    }
    g_was2[t] = s;
    g_wad2[t] = d;
    if (t < 2) { g_as1[2 * n + t] = -1e30f; g_ad1[2 * n + t] = 0.f; }
    if (t == 0) { g_as2[n] = -1e30f; g_ad2[n] = 0.f; }
    g_h1h[(size_t)n * F1 + t] = __float2half(0.f);
    if (t < OUTC) g_h2h[(size_t)n * OUTC + t] = __float2half(0.f);
}

// ---------------- layer-1 projection + logits (prescaled by log2e) -------------
__global__ void k1_proj(const float* __restrict__ x, const float* __restrict__ W1,
                        const float* __restrict__ attS, const float* __restrict__ attD, int n) {
    __shared__ __align__(16) float Ws[IN_DIM * F1];
    __shared__ __align__(16) float xsT[IN_DIM][36];
    int t = threadIdx.x;                                // 256
    for (int i = t; i < IN_DIM * F1; i += 256) Ws[i] = W1[i];
    int base = blockIdx.x * 32;
    #pragma unroll
    for (int i = 0; i < 4; ++i) {
        int idx = t + i * 256;
        int node = idx >> 5, k = idx & 31;
        int nn = base + node;
        xsT[k][node] = (nn < n) ? x[(size_t)nn * IN_DIM + k] : 0.f;
    }
    __syncthreads();
    int tx = t & 31;
    int ty = t >> 5;
    unsigned long long acc[4][2] = {};
    #pragma unroll
    for (int k = 0; k < IN_DIM; ++k) {
        ulonglong2 w = *(const ulonglong2*)&Ws[k * F1 + tx * 4];
        float4 xv = *(const float4*)&xsT[k][ty * 4];
        unsigned long long xp0 = packdup(xv.x), xp1 = packdup(xv.y);
        unsigned long long xp2 = packdup(xv.z), xp3 = packdup(xv.w);
        ffma2(acc[0][0], w.x, xp0); ffma2(acc[0][1], w.y, xp0);
        ffma2(acc[1][0], w.x, xp1); ffma2(acc[1][1], w.y, xp1);
        ffma2(acc[2][0], w.x, xp2); ffma2(acc[2][1], w.y, xp2);
        ffma2(acc[3][0], w.x, xp3); ffma2(acc[3][1], w.y, xp3);
    }
    float4 av = __ldg((const float4*)&attS[tx * 4]);
    float4 dv = __ldg((const float4*)&attD[tx * 4]);
    #pragma unroll
    for (int i = 0; i < 4; ++i) {
        int nn = base + ty * 4 + i;
        float f0 = lo32(acc[i][0]), f1 = hi32(acc[i][0]);
        float f2 = lo32(acc[i][1]), f3 = hi32(acc[i][1]);
        if (nn < n) {
            __half2 p01 = __floats2half2_rn(f0, f1);
            __half2 p23 = __floats2half2_rn(f2, f3);
            uint2 u;
            u.x = reinterpret_cast<unsigned&>(p01);
            u.y = reinterpret_cast<unsigned&>(p23);
            *(uint2*)(g_h1h + (size_t)nn * F1 + tx * 4) = u;
        }
        float ps = f0 * av.x + f1 * av.y + f2 * av.z + f3 * av.w;
        float pd = f0 * dv.x + f1 * dv.y + f2 * dv.z + f3 * dv.w;
        #pragma unroll
        for (int o = 8; o > 0; o >>= 1) {
            ps += __shfl_xor_sync(0xffffffffu, ps, o);
            pd += __shfl_xor_sync(0xffffffffu, pd, o);
        }
        if ((tx & 15) == 0 && nn < n) {
            g_as1[2 * nn + (tx >> 4)] = ps * LOG2E;
            g_ad1[2 * nn + (tx >> 4)] = pd * LOG2E;
        }
    }
}

// ------- layer-1 gather: 2 nodes/warp, 16 lanes/node, 8 ch/lane ----------------
__global__ void __launch_bounds__(128)
k_gather1(const float* __restrict__ bias1,
          const float* __restrict__ gamma,
          const float* __restrict__ beta, int n) {
    int warp = (blockIdx.x * blockDim.x + threadIdx.x) >> 5;
    int lane = threadIdx.x & 31;
    int half = lane >> 4;
    int sub  = lane & 15;
    int node = warp * 2 + half;
    bool valid = node < n;
    if (warp * 2 >= n) return;       // whole warp out of range
    int nd = valid ? node : n;       // dummy row (safe logits/features)
    int h = sub >> 3;                // lanes 0-7: head0 (ch 0..63), 8-15: head1
    float lad = g_ad1[2 * nd + h];
    float acc[8] = {}, accB[8] = {};
    float s = 0.f, sB = 0.f;
    // self-loop
    {
        float wv = exp2f(lrelu(g_as1[2 * nd + h] + lad));
        uint4 r = *(const uint4*)(g_h1h + (size_t)nd * F1 + sub * 8);
        float2 f;
        f = h2f2(r.x); acc[0] += wv * f.x; acc[1] += wv * f.y;
        f = h2f2(r.y); acc[2] += wv * f.x; acc[3] += wv * f.y;
        f = h2f2(r.z); acc[4] += wv * f.x; acc[5] += wv * f.y;
        f = h2f2(r.w); acc[6] += wv * f.x; acc[7] += wv * f.y;
        s += wv;
    }
    int e = 0, endp = 0;
    if (valid) { e = g_off[node]; endp = g_off[node + 1]; }   // padded to mult of 4
    for (; e < endp; e += 2) {
        int2 q = *(const int2*)&g_csr[e];
        float pA = g_as1[2 * q.x + h];
        float pB = g_as1[2 * q.y + h];
        uint4 rA = *(const uint4*)(g_h1h + (size_t)q.x * F1 + sub * 8);
        uint4 rB = *(const uint4*)(g_h1h + (size_t)q.y * F1 + sub * 8);
        float wA = exp2f(lrelu(pA + lad));
        float wB = exp2f(lrelu(pB + lad));
        float2 f;
        f = h2f2(rA.x); acc[0]  += wA * f.x; acc[1]  += wA * f.y;
        f = h2f2(rA.y); acc[2]  += wA * f.x; acc[3]  += wA * f.y;
        f = h2f2(rA.z); acc[4]  += wA * f.x; acc[5]  += wA * f.y;
        f = h2f2(rA.w); acc[6]  += wA * f.x; acc[7]  += wA * f.y;
        f = h2f2(rB.x); accB[0] += wB * f.x; accB[1] += wB * f.y;
        f = h2f2(rB.y); accB[2] += wB * f.x; accB[3] += wB * f.y;
        f = h2f2(rB.z); accB[4] += wB * f.x; accB[5] += wB * f.y;
        f = h2f2(rB.w); accB[6] += wB * f.x; accB[7] += wB * f.y;
        s += wA; sB += wB;
    }
    s += sB;
    float r = 1.f / s;
    int c = sub * 8;
    float4 bi0 = *(const float4*)&bias1[c];
    float4 bi1 = *(const float4*)&bias1[c + 4];
    float v[8];
    v[0] = (acc[0] + accB[0]) * r + bi0.x;
    v[1] = (acc[1] + accB[1]) * r + bi0.y;
    v[2] = (acc[2] + accB[2]) * r + bi0.z;
    v[3] = (acc[3] + accB[3]) * r + bi0.w;
    v[4] = (acc[4] + accB[4]) * r + bi1.x;
    v[5] = (acc[5] + accB[5]) * r + bi1.y;
    v[6] = (acc[6] + accB[6]) * r + bi1.z;
    v[7] = (acc[7] + accB[7]) * r + bi1.w;
    // LayerNorm over 128 channels (16 lanes x 8)
    float tot = 0.f;
    #pragma unroll
    for (int i = 0; i < 8; ++i) tot += v[i];
    #pragma unroll
    for (int o = 8; o > 0; o >>= 1) tot += __shfl_xor_sync(0xffffffffu, tot, o);
    float mu = tot * (1.f / 128.f);
    float sq = 0.f;
    float dv[8];
    #pragma unroll
    for (int i = 0; i < 8; ++i) { dv[i] = v[i] - mu; sq += dv[i] * dv[i]; }
    #pragma unroll
    for (int o = 8; o > 0; o >>= 1) sq += __shfl_xor_sync(0xffffffffu, sq, o);
    float inv = rsqrtf(sq * (1.f / 128.f) + 1e-5f);
    float4 gm0 = *(const float4*)&gamma[c];
    float4 gm1 = *(const float4*)&gamma[c + 4];
    float4 bt0 = *(const float4*)&beta[c];
    float4 bt1 = *(const float4*)&beta[c + 4];
    float y[8];
    y[0] = fmaxf(dv[0] * inv * gm0.x + bt0.x, 0.f);
    y[1] = fmaxf(dv[1] * inv * gm0.y + bt0.y, 0.f);
    y[2] = fmaxf(dv[2] * inv * gm0.z + bt0.z, 0.f);
    y[3] = fmaxf(dv[3] * inv * gm0.w + bt0.w, 0.f);
    y[4] = fmaxf(dv[4] * inv * gm1.x + bt1.x, 0.f);
    y[5] = fmaxf(dv[5] * inv * gm1.y + bt1.y, 0.f);
    y[6] = fmaxf(dv[6] * inv * gm1.z + bt1.z, 0.f);
    y[7] = fmaxf(dv[7] * inv * gm1.w + bt1.w, 0.f);
    if (valid) {
        __half2 p0 = __floats2half2_rn(y[0], y[1]);
        __half2 p1 = __floats2half2_rn(y[2], y[3]);
        __half2 p2 = __floats2half2_rn(y[4], y[5]);
        __half2 p3 = __floats2half2_rn(y[6], y[7]);
        uint4 u;
        u.x = reinterpret_cast<unsigned&>(p0);
        u.y = reinterpret_cast<unsigned&>(p1);
        u.z = reinterpret_cast<unsigned&>(p2);
        u.w = reinterpret_cast<unsigned&>(p3);
        *(uint4*)(g_hlnh + (size_t)node * F1 + c) = u;
    }
    // layer-2 logits
    float4 ws0 = *(const float4*)&g_was2[c];
    float4 ws1 = *(const float4*)&g_was2[c + 4];
    float4 wd0 = *(const float4*)&g_wad2[c];
    float4 wd1 = *(const float4*)&g_wad2[c + 4];
    float sa = y[0] * ws0.x + y[1] * ws0.y + y[2] * ws0.z + y[3] * ws0.w
             + y[4] * ws1.x + y[5] * ws1.y + y[6] * ws1.z + y[7] * ws1.w;
    float sd = y[0] * wd0.x + y[1] * wd0.y + y[2] * wd0.z + y[3] * wd0.w
             + y[4] * wd1.x + y[5] * wd1.y + y[6] * wd1.z + y[7] * wd1.w;
    #pragma unroll
    for (int o = 8; o > 0; o >>= 1) {
        sa += __shfl_xor_sync(0xffffffffu, sa, o);
        sd += __shfl_xor_sync(0xffffffffu, sd, o);
    }
    if (sub == 0 && valid) { g_as2[node] = sa * LOG2E; g_ad2[node] = sd * LOG2E; }
}

// ---------------- layer-2 projection: 64 nodes/block, 256 threads --------------
__global__ void __launch_bounds__(256)
k4_proj(const float* __restrict__ W2, int n) {
    __shared__ __align__(16) float Ws[F1 * OUTC];       // 32 KB
    __shared__ __half2 xsT[F1 / 2][65];
    int t = threadIdx.x;                                // 256
    for (int i = t; i < F1 * OUTC; i += 256) Ws[i] = W2[i];
    int base = blockIdx.x * 64;
    #pragma unroll
    for (int i = 0; i < 16; ++i) {
        int idx = t + i * 256;
        int node = idx >> 6, kk = idx & 63;
        int nn = base + node;
        xsT[kk][node] = (nn < n) ? ((const __half2*)g_hlnh)[(size_t)nn * 64 + kk]
                                 : __float2half2_rn(0.f);
    }
    __syncthreads();
    int tx = t & 15;
    int ty = t >> 4;
    unsigned long long acc[4][2] = {};
    #pragma unroll 4
    for (int kk = 0; kk < 64; ++kk) {
        ulonglong2 wA = *(const ulonglong2*)&Ws[(2 * kk)     * OUTC + tx * 4];
        ulonglong2 wB = *(const ulonglong2*)&Ws[(2 * kk + 1) * OUTC + tx * 4];
        #pragma unroll
        for (int i = 0; i < 4; ++i) {
            float2 f = __half22float2(xsT[kk][ty * 4 + i]);
            unsigned long long xp0 = packdup(f.x), xp1 = packdup(f.y);
            ffma2(acc[i][0], wA.x, xp0); ffma2(acc[i][0], wB.x, xp1);
            ffma2(acc[i][1], wA.y, xp0); ffma2(acc[i][1], wB.y, xp1);
        }
    }
    #pragma unroll
    for (int i = 0; i < 4; ++i) {
        int nn = base + ty * 4 + i;
        if (nn >= n) continue;
        __half2 p01 = __floats2half2_rn(lo32(acc[i][0]), hi32(acc[i][0]));
        __half2 p23 = __floats2half2_rn(lo32(acc[i][1]), hi32(acc[i][1]));
        uint2 u;
        u.x = reinterpret_cast<unsigned&>(p01);
        u.y = reinterpret_cast<unsigned&>(p23);
        *(uint2*)(g_h2h + (size_t)nn * OUTC + tx * 4) = u;
    }
}

// ------- layer-2 gather: 2 nodes/warp, 16 lanes/node, 4 ch/lane ----------------
__global__ void __launch_bounds__(128)
k_gather2(float* __restrict__ out, const float* __restrict__ bias2, int n) {
    int warp = (blockIdx.x * blockDim.x + threadIdx.x) >> 5;
    int lane = threadIdx.x & 31;
    int half = lane >> 4;
    int sub  = lane & 15;
    int node = warp * 2 + half;
    bool valid = node < n;
    if (warp * 2 >= n) return;
    int nd = valid ? node : n;
    float lad = g_ad2[nd];
    float acc[4] = {}, accB[4] = {};
    float s = 0.f, sB = 0.f;
    {
        float wv = exp2f(lrelu(g_as2[nd] + lad));
        uint2 rr = *(const uint2*)(g_h2h + (size_t)nd * OUTC + sub * 4);
        float2 f;
        f = h2f2(rr.x); acc[0] += wv * f.x; acc[1] += wv * f.y;
        f = h2f2(rr.y); acc[2] += wv * f.x; acc[3] += wv * f.y;
        s += wv;
    }
    int e = 0, endp = 0;
    if (valid) { e = g_off[node]; endp = g_off[node + 1]; }
    for (; e < endp; e += 2) {
        int2 q = *(const int2*)&g_csr[e];
        float pA = g_as2[q.x];
        float pB = g_as2[q.y];
        uint2 rA = *(const uint2*)(g_h2h + (size_t)q.x * OUTC + sub * 4);
        uint2 rB = *(const uint2*)(g_h2h + (size_t)q.y * OUTC + sub * 4);
        float wA = exp2f(lrelu(pA + lad));
        float wB = exp2f(lrelu(pB + lad));
        float2 f;
        f = h2f2(rA.x); acc[0]  += wA * f.x; acc[1]  += wA * f.y;
        f = h2f2(rA.y); acc[2]  += wA * f.x; acc[3]  += wA * f.y;
        f = h2f2(rB.x); accB[0] += wB * f.x; accB[1] += wB * f.y;
        f = h2f2(rB.y); accB[2] += wB * f.x; accB[3] += wB * f.y;
        s += wA; sB += wB;
    }
    s += sB;
    float r = 1.f / s;
    int c = sub * 4;
    float4 bi = *(const float4*)&bias2[c];
    if (valid) {
        float4 o;
        o.x = (acc[0] + accB[0]) * r + bi.x;
        o.y = (acc[1] + accB[1]) * r + bi.y;
        o.z = (acc[2] + accB[2]) * r + bi.z;
        o.w = (acc[3] + accB[3]) * r + bi.w;
        *(float4*)(out + (size_t)node * OUTC + c) = o;
    }
}

// ---------------- launcher -----------------------------------------------------
extern "C" void kernel_launch(void* const* d_in, const int* in_sizes, int n_in,
                              void* d_out, int out_size) {
    const float* x     = (const float*)d_in[0];
    const int*   ei    = (const int*)  d_in[1];
    const float* W1    = (const float*)d_in[2];
    const float* as1   = (const float*)d_in[3];
    const float* ad1   = (const float*)d_in[4];
    const float* b1    = (const float*)d_in[5];
    const float* gamma = (const float*)d_in[6];
    const float* beta  = (const float*)d_in[7];
    const float* W2    = (const float*)d_in[8];
    const float* as2   = (const float*)d_in[9];
    const float* ad2   = (const float*)d_in[10];
    const float* b2    = (const float*)d_in[11];
    float* out = (float*)d_out;

    int n = in_sizes[0] / IN_DIM;
    int E = in_sizes[1] / 2;
    const int* srcp = ei;
    const int* dstp = ei + E;

    int gwarps = (n + 1) / 2;                 // 2 nodes per warp
    int gblocks = (gwarps + 3) / 4;           // 4 warps per 128-thr block

    k_csr<<<CSR_BLOCKS, CSR_THREADS>>>(srcp, dstp, E, n);          // 1
    k_fold2<<<1, 128>>>(W2, as2, ad2, n);                          // 2
    k1_proj<<<(n + 31) / 32, 256>>>(x, W1, as1, ad1, n);           // 3
    k_gather1<<<gblocks, 128>>>(b1, gamma, beta, n);               // 4 <- profiled
    k4_proj<<<(n + 63) / 64, 256>>>(W2, n);                        // 5
    k_gather2<<<gblocks, 128>>>(out, b2, n);                       // 6
}

// round 9
// speedup vs baseline: 1.2897x; 1.1194x over previous
#include <cuda_runtime.h>
#include <cuda_fp16.h>

#define N_NODES 100000
#define E_EDGES 1600000
#define IN_DIM 32
#define HID 64
#define NHEADS 2
#define F1 128   // NHEADS*HID
#define OUTC 64
#define LOG2E 1.4426950408889634f

#define CSR_BLOCKS 512
#define CSR_THREADS 256

// ---------------- scratch (device globals; no allocation allowed) ------------
__device__ __align__(16) __half g_h1h [(size_t)(N_NODES + 1) * F1];
__device__ __align__(16) __half g_hlnh[(size_t)N_NODES * F1];
__device__ __align__(16) __half g_h2h [(size_t)(N_NODES + 1) * OUTC];
__device__ __align__(16) float g_as1[(N_NODES + 1) * NHEADS];
__device__ __align__(16) float g_ad1[(N_NODES + 1) * NHEADS];
__device__ float g_as2[N_NODES + 1];
__device__ float g_ad2[N_NODES + 1];
__device__ int   g_deg[N_NODES];
__device__ int   g_off[N_NODES + 1];
__device__ int   g_cur[N_NODES];
__device__ __align__(16) int g_csr[E_EDGES + 3 * N_NODES + 8];
__device__ int   g_bsum[CSR_BLOCKS];
__device__ int   g_bscan[CSR_BLOCKS];
__device__ __align__(16) float g_was2[F1];
__device__ __align__(16) float g_wad2[F1];
__device__ int   g_bar_count;
__device__ int   g_bar_gen;

__device__ __forceinline__ float lrelu(float v) { return v > 0.f ? v : 0.2f * v; }

// ---- packed fp32x2 helpers ----------------------------------------------------
__device__ __forceinline__ unsigned long long packdup(float a) {
    unsigned long long r;
    asm("mov.b64 %0, {%1, %1};" : "=l"(r) : "f"(a));
    return r;
}
__device__ __forceinline__ void ffma2(unsigned long long& acc,
                                      unsigned long long a, unsigned long long b) {
    asm("fma.rn.f32x2 %0, %1, %2, %0;" : "+l"(acc) : "l"(a), "l"(b));
}
__device__ __forceinline__ float lo32(unsigned long long v) {
    return __uint_as_float((unsigned)(v & 0xffffffffull));
}
__device__ __forceinline__ float hi32(unsigned long long v) {
    return __uint_as_float((unsigned)(v >> 32));
}
__device__ __forceinline__ float2 h2f2(unsigned h) {
    return __half22float2(reinterpret_cast<__half2&>(h));
}

// ---- software grid barrier (csr blocks only) -----------------------------------
__device__ __forceinline__ void gsync() {
    __syncthreads();
    __threadfence();
    if (threadIdx.x == 0) {
        int gen = *(volatile int*)&g_bar_gen;
        if (atomicAdd(&g_bar_count, 1) == CSR_BLOCKS - 1) {
            g_bar_count = 0;
            __threadfence();
            *(volatile int*)&g_bar_gen = gen + 1;
        } else {
            while (*(volatile int*)&g_bar_gen == gen) { }
        }
        __threadfence();
    }
    __syncthreads();
}

// ===== mega kernel: blocks [0,512) build CSR; blocks [512,...) do fold2+proj1 ===
__global__ void __launch_bounds__(256, 4)
k_mega(const int* __restrict__ src, const int* __restrict__ dst, int E, int n,
       const float* __restrict__ x, const float* __restrict__ W1,
       const float* __restrict__ attS, const float* __restrict__ attD,
       const float* __restrict__ W2,
       const float* __restrict__ as2v, const float* __restrict__ ad2v) {
    __shared__ __align__(16) float Ws[IN_DIM * F1];      // proj: weights | csr: wsum alias
    __shared__ __align__(16) float xsT[IN_DIM][36];
    int t = threadIdx.x;

    if (blockIdx.x < CSR_BLOCKS) {
        // -------------------- CSR path --------------------
        int* wsum = (int*)xsT;
        const int T = CSR_BLOCKS * CSR_THREADS;
        int gt = blockIdx.x * CSR_THREADS + t;
        int lane = t & 31, w = t >> 5;

        for (int i = gt; i < n; i += T) g_deg[i] = 0;
        gsync();
        int E4 = E >> 2;
        for (int i = gt; i < E4; i += T) {
            int4 d4 = ((const int4*)dst)[i];
            atomicAdd(&g_deg[d4.x], 1);
            atomicAdd(&g_deg[d4.y], 1);
            atomicAdd(&g_deg[d4.z], 1);
            atomicAdd(&g_deg[d4.w], 1);
        }
        for (int e = E4 * 4 + gt; e < E; e += T) atomicAdd(&g_deg[dst[e]], 1);
        gsync();
        int C = (n + T - 1) / T;
        int b0 = gt * C;
        int s = 0;
        for (int i = 0; i < C; ++i) {
            int idx = b0 + i;
            if (idx < n) s += (g_deg[idx] + 3) & ~3;
        }
        int incl = s;
        #pragma unroll
        for (int o = 1; o < 32; o <<= 1) {
            int xv = __shfl_up_sync(0xffffffffu, incl, o);
            if (lane >= o) incl += xv;
        }
        if (lane == 31) wsum[w] = incl;
        __syncthreads();
        if (t < 8) {
            int xv = wsum[t];
            #pragma unroll
            for (int o = 1; o < 8; o <<= 1) {
                int y = __shfl_up_sync(0xffu, xv, o);
                if (t >= o) xv += y;
            }
            wsum[t] = xv;
        }
        __syncthreads();
        int excl = incl - s + (w > 0 ? wsum[w - 1] : 0);
        if (t == CSR_THREADS - 1) g_bsum[blockIdx.x] = excl + s;
        gsync();
        if (blockIdx.x == 0) {
            int a0 = g_bsum[2 * t], a1 = g_bsum[2 * t + 1];
            int ss = a0 + a1;
            int in2 = ss;
            #pragma unroll
            for (int o = 1; o < 32; o <<= 1) {
                int xv = __shfl_up_sync(0xffffffffu, in2, o);
                if (lane >= o) in2 += xv;
            }
            if (lane == 31) wsum[w] = in2;
            __syncthreads();
            if (t < 8) {
                int xv = wsum[t];
                #pragma unroll
                for (int o = 1; o < 8; o <<= 1) {
                    int y = __shfl_up_sync(0xffu, xv, o);
                    if (t >= o) xv += y;
                }
                wsum[t] = xv;
            }
            __syncthreads();
            int ex2 = in2 - ss + (w > 0 ? wsum[w - 1] : 0);
            g_bscan[2 * t]     = ex2;
            g_bscan[2 * t + 1] = ex2 + a0;
        }
        gsync();
        int off = excl + g_bscan[blockIdx.x];
        for (int i = 0; i < C; ++i) {
            int idx = b0 + i;
            if (idx < n) {
                int d = g_deg[idx];
                int p = (d + 3) & ~3;
                g_off[idx] = off;
                g_cur[idx] = off;
                for (int j = d; j < p; ++j) g_csr[off + j] = n;  // dummy
                if (idx == n - 1) g_off[n] = off + p;
                off += p;
            }
        }
        gsync();
        for (int i = gt; i < E4; i += T) {
            int4 s4 = ((const int4*)src)[i];
            int4 d4 = ((const int4*)dst)[i];
            g_csr[atomicAdd(&g_cur[d4.x], 1)] = s4.x;
            g_csr[atomicAdd(&g_cur[d4.y], 1)] = s4.y;
            g_csr[atomicAdd(&g_cur[d4.z], 1)] = s4.z;
            g_csr[atomicAdd(&g_cur[d4.w], 1)] = s4.w;
        }
        for (int e = E4 * 4 + gt; e < E; e += T) {
            g_csr[atomicAdd(&g_cur[dst[e]], 1)] = src[e];
        }
        return;
    }

    // -------------------- fold2 + proj1 path --------------------
    int pb = blockIdx.x - CSR_BLOCKS;
    if (pb == 0) {
        if (t < F1) {
            float s = 0.f, d = 0.f;
            for (int c = 0; c < OUTC; ++c) {
                float wv = W2[t * OUTC + c];
                s += wv * as2v[c];
                d += wv * ad2v[c];
            }
            g_was2[t] = s;
            g_wad2[t] = d;
            g_h1h[(size_t)n * F1 + t] = __float2half(0.f);
        }
        if (t < 2) { g_as1[2 * n + t] = -1e30f; g_ad1[2 * n + t] = 0.f; }
        if (t == 0) { g_as2[n] = -1e30f; g_ad2[n] = 0.f; }
        if (t < OUTC) g_h2h[(size_t)n * OUTC + t] = __float2half(0.f);
    }
    for (int i = t; i < IN_DIM * F1; i += 256) Ws[i] = W1[i];
    int base = pb * 32;
    #pragma unroll
    for (int i = 0; i < 4; ++i) {
        int idx = t + i * 256;
        int node = idx >> 5, k = idx & 31;
        int nn = base + node;
        xsT[k][node] = (nn < n) ? x[(size_t)nn * IN_DIM + k] : 0.f;
    }
    __syncthreads();
    int tx = t & 31;
    int ty = t >> 5;
    unsigned long long acc[4][2] = {};
    #pragma unroll
    for (int k = 0; k < IN_DIM; ++k) {
        ulonglong2 w = *(const ulonglong2*)&Ws[k * F1 + tx * 4];
        float4 xv = *(const float4*)&xsT[k][ty * 4];
        unsigned long long xp0 = packdup(xv.x), xp1 = packdup(xv.y);
        unsigned long long xp2 = packdup(xv.z), xp3 = packdup(xv.w);
        ffma2(acc[0][0], w.x, xp0); ffma2(acc[0][1], w.y, xp0);
        ffma2(acc[1][0], w.x, xp1); ffma2(acc[1][1], w.y, xp1);
        ffma2(acc[2][0], w.x, xp2); ffma2(acc[2][1], w.y, xp2);
        ffma2(acc[3][0], w.x, xp3); ffma2(acc[3][1], w.y, xp3);
    }
    float4 av = __ldg((const float4*)&attS[tx * 4]);
    float4 dvv = __ldg((const float4*)&attD[tx * 4]);
    #pragma unroll
    for (int i = 0; i < 4; ++i) {
        int nn = base + ty * 4 + i;
        float f0 = lo32(acc[i][0]), f1 = hi32(acc[i][0]);
        float f2 = lo32(acc[i][1]), f3 = hi32(acc[i][1]);
        if (nn < n) {
            __half2 p01 = __floats2half2_rn(f0, f1);
            __half2 p23 = __floats2half2_rn(f2, f3);
            uint2 u;
            u.x = reinterpret_cast<unsigned&>(p01);
            u.y = reinterpret_cast<unsigned&>(p23);
            *(uint2*)(g_h1h + (size_t)nn * F1 + tx * 4) = u;
        }
        float ps = f0 * av.x + f1 * av.y + f2 * av.z + f3 * av.w;
        float pd = f0 * dvv.x + f1 * dvv.y + f2 * dvv.z + f3 * dvv.w;
        #pragma unroll
        for (int o = 8; o > 0; o >>= 1) {
            ps += __shfl_xor_sync(0xffffffffu, ps, o);
            pd += __shfl_xor_sync(0xffffffffu, pd, o);
        }
        if ((tx & 15) == 0 && nn < n) {
            g_as1[2 * nn + (tx >> 4)] = ps * LOG2E;
            g_ad1[2 * nn + (tx >> 4)] = pd * LOG2E;
        }
    }
}

// ------- layer-1 gather: 2 nodes/warp, 16 lanes/node, 8 ch/lane ----------------
__global__ void __launch_bounds__(128)
k_gather1(const float* __restrict__ bias1,
          const float* __restrict__ gamma,
          const float* __restrict__ beta, int n) {
    int warp = (blockIdx.x * blockDim.x + threadIdx.x) >> 5;
    int lane = threadIdx.x & 31;
    int half = lane >> 4;
    int sub  = lane & 15;
    int node = warp * 2 + half;
    bool valid = node < n;
    if (warp * 2 >= n) return;
    int nd = valid ? node : n;
    int h = sub >> 3;
    float lad = g_ad1[2 * nd + h];
    float acc[8] = {}, accB[8] = {};
    float s = 0.f, sB = 0.f;
    // self-loop
    {
        float wv = exp2f(lrelu(g_as1[2 * nd + h] + lad));
        uint4 r = *(const uint4*)(g_h1h + (size_t)nd * F1 + sub * 8);
        float2 f;
        f = h2f2(r.x); acc[0] += wv * f.x; acc[1] += wv * f.y;
        f = h2f2(r.y); acc[2] += wv * f.x; acc[3] += wv * f.y;
        f = h2f2(r.z); acc[4] += wv * f.x; acc[5] += wv * f.y;
        f = h2f2(r.w); acc[6] += wv * f.x; acc[7] += wv * f.y;
        s += wv;
    }
    int e = 0, endp = 0;
    if (valid) { e = g_off[node]; endp = g_off[node + 1]; }
    for (; e < endp; e += 2) {
        int2 q = *(const int2*)&g_csr[e];
        float pA = g_as1[2 * q.x + h];
        float pB = g_as1[2 * q.y + h];
        uint4 rA = *(const uint4*)(g_h1h + (size_t)q.x * F1 + sub * 8);
        uint4 rB = *(const uint4*)(g_h1h + (size_t)q.y * F1 + sub * 8);
        float wA = exp2f(lrelu(pA + lad));
        float wB = exp2f(lrelu(pB + lad));
        float2 f;
        f = h2f2(rA.x); acc[0]  += wA * f.x; acc[1]  += wA * f.y;
        f = h2f2(rA.y); acc[2]  += wA * f.x; acc[3]  += wA * f.y;
        f = h2f2(rA.z); acc[4]  += wA * f.x; acc[5]  += wA * f.y;
        f = h2f2(rA.w); acc[6]  += wA * f.x; acc[7]  += wA * f.y;
        f = h2f2(rB.x); accB[0] += wB * f.x; accB[1] += wB * f.y;
        f = h2f2(rB.y); accB[2] += wB * f.x; accB[3] += wB * f.y;
        f = h2f2(rB.z); accB[4] += wB * f.x; accB[5] += wB * f.y;
        f = h2f2(rB.w); accB[6] += wB * f.x; accB[7] += wB * f.y;
        s += wA; sB += wB;
    }
    s += sB;
    float r = 1.f / s;
    int c = sub * 8;
    float4 bi0 = *(const float4*)&bias1[c];
    float4 bi1 = *(const float4*)&bias1[c + 4];
    float v[8];
    v[0] = (acc[0] + accB[0]) * r + bi0.x;
    v[1] = (acc[1] + accB[1]) * r + bi0.y;
    v[2] = (acc[2] + accB[2]) * r + bi0.z;
    v[3] = (acc[3] + accB[3]) * r + bi0.w;
    v[4] = (acc[4] + accB[4]) * r + bi1.x;
    v[5] = (acc[5] + accB[5]) * r + bi1.y;
    v[6] = (acc[6] + accB[6]) * r + bi1.z;
    v[7] = (acc[7] + accB[7]) * r + bi1.w;
    float tot = 0.f;
    #pragma unroll
    for (int i = 0; i < 8; ++i) tot += v[i];
    #pragma unroll
    for (int o = 8; o > 0; o >>= 1) tot += __shfl_xor_sync(0xffffffffu, tot, o);
    float mu = tot * (1.f / 128.f);
    float sq = 0.f;
    float dv[8];
    #pragma unroll
    for (int i = 0; i < 8; ++i) { dv[i] = v[i] - mu; sq += dv[i] * dv[i]; }
    #pragma unroll
    for (int o = 8; o > 0; o >>= 1) sq += __shfl_xor_sync(0xffffffffu, sq, o);
    float inv = rsqrtf(sq * (1.f / 128.f) + 1e-5f);
    float4 gm0 = *(const float4*)&gamma[c];
    float4 gm1 = *(const float4*)&gamma[c + 4];
    float4 bt0 = *(const float4*)&beta[c];
    float4 bt1 = *(const float4*)&beta[c + 4];
    float y[8];
    y[0] = fmaxf(dv[0] * inv * gm0.x + bt0.x, 0.f);
    y[1] = fmaxf(dv[1] * inv * gm0.y + bt0.y, 0.f);
    y[2] = fmaxf(dv[2] * inv * gm0.z + bt0.z, 0.f);
    y[3] = fmaxf(dv[3] * inv * gm0.w + bt0.w, 0.f);
    y[4] = fmaxf(dv[4] * inv * gm1.x + bt1.x, 0.f);
    y[5] = fmaxf(dv[5] * inv * gm1.y + bt1.y, 0.f);
    y[6] = fmaxf(dv[6] * inv * gm1.z + bt1.z, 0.f);
    y[7] = fmaxf(dv[7] * inv * gm1.w + bt1.w, 0.f);
    if (valid) {
        __half2 p0 = __floats2half2_rn(y[0], y[1]);
        __half2 p1 = __floats2half2_rn(y[2], y[3]);
        __half2 p2 = __floats2half2_rn(y[4], y[5]);
        __half2 p3 = __floats2half2_rn(y[6], y[7]);
        uint4 u;
        u.x = reinterpret_cast<unsigned&>(p0);
        u.y = reinterpret_cast<unsigned&>(p1);
        u.z = reinterpret_cast<unsigned&>(p2);
        u.w = reinterpret_cast<unsigned&>(p3);
        *(uint4*)(g_hlnh + (size_t)node * F1 + c) = u;
    }
    float4 ws0 = *(const float4*)&g_was2[c];
    float4 ws1 = *(const float4*)&g_was2[c + 4];
    float4 wd0 = *(const float4*)&g_wad2[c];
    float4 wd1 = *(const float4*)&g_wad2[c + 4];
    float sa = y[0] * ws0.x + y[1] * ws0.y + y[2] * ws0.z + y[3] * ws0.w
             + y[4] * ws1.x + y[5] * ws1.y + y[6] * ws1.z + y[7] * ws1.w;
    float sd = y[0] * wd0.x + y[1] * wd0.y + y[2] * wd0.z + y[3] * wd0.w
             + y[4] * wd1.x + y[5] * wd1.y + y[6] * wd1.z + y[7] * wd1.w;
    #pragma unroll
    for (int o = 8; o > 0; o >>= 1) {
        sa += __shfl_xor_sync(0xffffffffu, sa, o);
        sd += __shfl_xor_sync(0xffffffffu, sd, o);
    }
    if (sub == 0 && valid) { g_as2[node] = sa * LOG2E; g_ad2[node] = sd * LOG2E; }
}

// ---------------- layer-2 projection: 64 nodes/block, 256 threads --------------
__global__ void __launch_bounds__(256)
k4_proj(const float* __restrict__ W2, int n) {
    __shared__ __align__(16) float Ws[F1 * OUTC];       // 32 KB
    __shared__ __half2 xsT[F1 / 2][65];
    int t = threadIdx.x;                                // 256
    for (int i = t; i < F1 * OUTC; i += 256) Ws[i] = W2[i];
    int base = blockIdx.x * 64;
    #pragma unroll
    for (int i = 0; i < 16; ++i) {
        int idx = t + i * 256;
        int node = idx >> 6, kk = idx & 63;
        int nn = base + node;
        xsT[kk][node] = (nn < n) ? ((const __half2*)g_hlnh)[(size_t)nn * 64 + kk]
                                 : __float2half2_rn(0.f);
    }
    __syncthreads();
    int tx = t & 15;
    int ty = t >> 4;
    unsigned long long acc[4][2] = {};
    #pragma unroll 4
    for (int kk = 0; kk < 64; ++kk) {
        ulonglong2 wA = *(const ulonglong2*)&Ws[(2 * kk)     * OUTC + tx * 4];
        ulonglong2 wB = *(const ulonglong2*)&Ws[(2 * kk + 1) * OUTC + tx * 4];
        #pragma unroll
        for (int i = 0; i < 4; ++i) {
            float2 f = __half22float2(xsT[kk][ty * 4 + i]);
            unsigned long long xp0 = packdup(f.x), xp1 = packdup(f.y);
            ffma2(acc[i][0], wA.x, xp0); ffma2(acc[i][0], wB.x, xp1);
            ffma2(acc[i][1], wA.y, xp0); ffma2(acc[i][1], wB.y, xp1);
        }
    }
    #pragma unroll
    for (int i = 0; i < 4; ++i) {
        int nn = base + ty * 4 + i;
        if (nn >= n) continue;
        __half2 p01 = __floats2half2_rn(lo32(acc[i][0]), hi32(acc[i][0]));
        __half2 p23 = __floats2half2_rn(lo32(acc[i][1]), hi32(acc[i][1]));
        uint2 u;
        u.x = reinterpret_cast<unsigned&>(p01);
        u.y = reinterpret_cast<unsigned&>(p23);
        *(uint2*)(g_h2h + (size_t)nn * OUTC + tx * 4) = u;
    }
}

// ------- layer-2 gather: 4 nodes/warp, 8 lanes/node, 8 ch/lane -----------------
__global__ void __launch_bounds__(128)
k_gather2(float* __restrict__ out, const float* __restrict__ bias2, int n) {
    int warp = (blockIdx.x * blockDim.x + threadIdx.x) >> 5;
    int lane = threadIdx.x & 31;
    int quad = lane >> 3;        // 0..3
    int sub  = lane & 7;         // 0..7
    int node = warp * 4 + quad;
    bool valid = node < n;
    if (warp * 4 >= n) return;
    int nd = valid ? node : n;
    float lad = g_ad2[nd];
    float acc[8] = {}, accB[8] = {};
    float s = 0.f, sB = 0.f;
    {
        float wv = exp2f(lrelu(g_as2[nd] + lad));
        uint4 r = *(const uint4*)(g_h2h + (size_t)nd * OUTC + sub * 8);
        float2 f;
        f = h2f2(r.x); acc[0] += wv * f.x; acc[1] += wv * f.y;
        f = h2f2(r.y); acc[2] += wv * f.x; acc[3] += wv * f.y;
        f = h2f2(r.z); acc[4] += wv * f.x; acc[5] += wv * f.y;
        f = h2f2(r.w); acc[6] += wv * f.x; acc[7] += wv * f.y;
        s += wv;
    }
    int e = 0, endp = 0;
    if (valid) { e = g_off[node]; endp = g_off[node + 1]; }
    for (; e < endp; e += 2) {
        int2 q = *(const int2*)&g_csr[e];
        float pA = g_as2[q.x];
        float pB = g_as2[q.y];
        uint4 rA = *(const uint4*)(g_h2h + (size_t)q.x * OUTC + sub * 8);
        uint4 rB = *(const uint4*)(g_h2h + (size_t)q.y * OUTC + sub * 8);
        float wA = exp2f(lrelu(pA + lad));
        float wB = exp2f(lrelu(pB + lad));
        float2 f;
        f = h2f2(rA.x); acc[0]  += wA * f.x; acc[1]  += wA * f.y;
        f = h2f2(rA.y); acc[2]  += wA * f.x; acc[3]  += wA * f.y;
        f = h2f2(rA.z); acc[4]  += wA * f.x; acc[5]  += wA * f.y;
        f = h2f2(rA.w); acc[6]  += wA * f.x; acc[7]  += wA * f.y;
        f = h2f2(rB.x); accB[0] += wB * f.x; accB[1] += wB * f.y;
        f = h2f2(rB.y); accB[2] += wB * f.x; accB[3] += wB * f.y;
        f = h2f2(rB.z); accB[4] += wB * f.x; accB[5] += wB * f.y;
        f = h2f2(rB.w); accB[6] += wB * f.x; accB[7] += wB * f.y;
        s += wA; sB += wB;
    }
    s += sB;
    if (valid) {
        float r = 1.f / s;
        int c = sub * 8;
        float4 bi0 = *(const float4*)&bias2[c];
        float4 bi1 = *(const float4*)&bias2[c + 4];
        float4 o0, o1;
        o0.x = (acc[0] + accB[0]) * r + bi0.x;
        o0.y = (acc[1] + accB[1]) * r + bi0.y;
        o0.z = (acc[2] + accB[2]) * r + bi0.z;
        o0.w = (acc[3] + accB[3]) * r + bi0.w;
        o1.x = (acc[4] + accB[4]) * r + bi1.x;
        o1.y = (acc[5] + accB[5]) * r + bi1.y;
        o1.z = (acc[6] + accB[6]) * r + bi1.z;
        o1.w = (acc[7] + accB[7]) * r + bi1.w;
        *(float4*)(out + (size_t)node * OUTC + c)     = o0;
        *(float4*)(out + (size_t)node * OUTC + c + 4) = o1;
    }
}

// ---------------- launcher -----------------------------------------------------
extern "C" void kernel_launch(void* const* d_in, const int* in_sizes, int n_in,
                              void* d_out, int out_size) {
    const float* x     = (const float*)d_in[0];
    const int*   ei    = (const int*)  d_in[1];
    const float* W1    = (const float*)d_in[2];
    const float* as1   = (const float*)d_in[3];
    const float* ad1   = (const float*)d_in[4];
    const float* b1    = (const float*)d_in[5];
    const float* gamma = (const float*)d_in[6];
    const float* beta  = (const float*)d_in[7];
    const float* W2    = (const float*)d_in[8];
    const float* as2   = (const float*)d_in[9];
    const float* ad2   = (const float*)d_in[10];
    const float* b2    = (const float*)d_in[11];
    float* out = (float*)d_out;

    int n = in_sizes[0] / IN_DIM;
    int E = in_sizes[1] / 2;
    const int* srcp = ei;
    const int* dstp = ei + E;

    int proj_blocks = (n + 31) / 32;
    int g1_blocks = (((n + 1) / 2) + 3) / 4;     // 2 nodes/warp, 4 warps/block
    int g2_blocks = (((n + 3) / 4) + 3) / 4;     // 4 nodes/warp, 4 warps/block

    k_mega<<<CSR_BLOCKS + proj_blocks, 256>>>(srcp, dstp, E, n,
                                              x, W1, as1, ad1, W2, as2, ad2);  // 1
    k_gather1<<<g1_blocks, 128>>>(b1, gamma, beta, n);                         // 2
    k4_proj<<<(n + 63) / 64, 256>>>(W2, n);                                    // 3
    k_gather2<<<g2_blocks, 128>>>(out, b2, n);                                 // 4 <- profiled
}